// round 4
// baseline (speedup 1.0000x reference)
#include <cuda_runtime.h>

// Problem dims
#define B_  64
#define T_  2048
#define IN_ 256
#define H_  512
#define C_  128

// Scan config: 16 clusters x 8 CTAs, 4 batches/cluster, 64 H-rows/CTA
#define CLUSTER_S 8
#define JS        64      // H_/CLUSTER_S rows of W_hh per CTA
#define GBATCH    4       // batches per cluster
#define KC        8       // k-chunks per row
#define KPT       64      // k elements per thread (H_/KC)
#define HPAD      68      // chunk padded to 68 floats -> conflict-free LDS.128
#define SCAN_THREADS 512

// Scratch ping-pong buffers (device globals: allocation-free)
__device__ float g_bufA[(size_t)B_ * T_ * H_];
__device__ float g_bufB[(size_t)B_ * T_ * H_];

static __device__ __forceinline__ unsigned smem_u32(const void* p) {
    unsigned r;
    asm("{ .reg .u64 t; cvta.to.shared.u64 t, %1; cvt.u32.u64 %0, t; }"
        : "=r"(r) : "l"(p));
    return r;
}

// packed fp32x2 FMA: d = a*b + d
static __device__ __forceinline__ void ffma2(unsigned long long& d,
                                             unsigned long long a,
                                             unsigned long long b) {
    asm("fma.rn.f32x2 %0, %1, %2, %0;" : "+l"(d) : "l"(a), "l"(b));
}

static __device__ __forceinline__ float hadd2(unsigned long long a) {
    float lo = __uint_as_float((unsigned)(a & 0xffffffffull));
    float hi = __uint_as_float((unsigned)(a >> 32));
    return lo + hi;
}

static __device__ __forceinline__ unsigned long long dupf(float f) {
    unsigned long long r;
    asm("mov.b64 %0, {%1, %1};" : "=l"(r) : "f"(f));
    return r;
}

// ---------------------------------------------------------------------------
// Recurrent scan: h_t = relu(pre_t + W_hh @ h_{t-1}).
// 16 clusters x 8 CTAs x 512 threads. Thread layout: tid = j*8 + kc, so one
// warp = 4 output rows x 8 kc-chunks. W[rank*64+j][kc*64..+63] in 32 packed
// f32x2 registers. h double-buffered in SMEM as 8 chunks of 68 floats
// (padded -> conflict-free). Per step: 4 batch dot-partials, butterfly
// shuffle-reduce over kc lanes, lanes kc<4 apply bias+relu for batch=kc and
// replicate the value to all 8 cluster CTAs via st.async + mbarrier tx
// accounting. NO __syncthreads / cluster barrier in the steady-state loop:
// each warp's stores are data-dependent on its reads, and wait(t) counts
// every warp's bytes, so step t+1 stores can't pass step t reads.
// ---------------------------------------------------------------------------
__global__ void __launch_bounds__(SCAN_THREADS, 1) __cluster_dims__(CLUSTER_S, 1, 1)
scan_kernel(const float* __restrict__ W_hh, const float* __restrict__ pre,
            float* __restrict__ hout)
{
    __shared__ float Hs[2][GBATCH][KC][HPAD];    // ~17.4 KB
    __shared__ __align__(8) unsigned long long mbar;

    const int tid  = threadIdx.x;
    const int rank = blockIdx.x & (CLUSTER_S - 1);
    const int bg   = blockIdx.x >> 3;
    const int kc   = tid & 7;           // k-chunk (lane bits 0..2)
    const int j    = tid >> 3;          // local output row 0..63

    // W slice into registers: 32 packed f32x2 = 64 fp32
    unsigned long long w[KPT / 2];
    {
        const float* wsrc = W_hh + (size_t)(rank * JS + j) * H_ + kc * KPT;
        #pragma unroll
        for (int i = 0; i < KPT / 2; i++)
            w[i] = *reinterpret_cast<const unsigned long long*>(wsrc + 2 * i);
    }

    // h_0 = 0 in both buffers
    for (int i = tid; i < 2 * GBATCH * KC * HPAD; i += SCAN_THREADS)
        (&Hs[0][0][0][0])[i] = 0.f;

    const unsigned mbar_l = smem_u32(&mbar);
    if (tid == 0)
        asm volatile("mbarrier.init.shared.b64 [%0], 1;" :: "r"(mbar_l) : "memory");

    // This lane's store slot (valid for kc<4): batch = kc, chunk = rank, off = j
    const int bsel = kc & 3;
    unsigned lh0 = smem_u32(&Hs[0][bsel][rank][j]);
    unsigned lh1 = smem_u32(&Hs[1][bsel][rank][j]);
    unsigned rh[2][CLUSTER_S], rmb[CLUSTER_S];
    #pragma unroll
    for (int r = 0; r < CLUSTER_S; r++) {
        asm("mapa.shared::cluster.u32 %0, %1, %2;" : "=r"(rh[0][r]) : "r"(lh0), "r"(r));
        asm("mapa.shared::cluster.u32 %0, %1, %2;" : "=r"(rh[1][r]) : "r"(lh1), "r"(r));
        asm("mapa.shared::cluster.u32 %0, %1, %2;" : "=r"(rmb[r])   : "r"(mbar_l), "r"(r));
    }

    __syncthreads();
    asm volatile("barrier.cluster.arrive.aligned;" ::: "memory");
    asm volatile("barrier.cluster.wait.aligned;"   ::: "memory");

    const int bred = bg * GBATCH + bsel;
    const float* preP  = pre  + (size_t)bred * T_ * H_ + rank * JS + j;
    float*       houtP = hout + (size_t)bred * T_ * H_ + rank * JS + j;
    float pv = (kc < 4) ? *preP : 0.f;   // pre for t=0

    int cur = 0;

    #pragma unroll 1
    for (int t = 0; t < T_; ++t) {
        // ---- partial dots for 4 batches (chunk kc), 4 independent chains
        const ulonglong2* hp = reinterpret_cast<const ulonglong2*>(
            &Hs[cur][0][kc][0]);
        unsigned long long a0 = 0ull, a1 = 0ull, a2 = 0ull, a3 = 0ull;
        #pragma unroll
        for (int i = 0; i < KPT / 4; i++) {
            ulonglong2 v0 = hp[i];            // batch stride = KC*HPAD/4 = 136
            ulonglong2 v1 = hp[i + 136];
            ulonglong2 v2 = hp[i + 272];
            ulonglong2 v3 = hp[i + 408];
            ffma2(a0, w[2 * i], v0.x); ffma2(a0, w[2 * i + 1], v0.y);
            ffma2(a1, w[2 * i], v1.x); ffma2(a1, w[2 * i + 1], v1.y);
            ffma2(a2, w[2 * i], v2.x); ffma2(a2, w[2 * i + 1], v2.y);
            ffma2(a3, w[2 * i], v3.x); ffma2(a3, w[2 * i + 1], v3.y);
        }
        float s0 = hadd2(a0), s1 = hadd2(a1), s2 = hadd2(a2), s3 = hadd2(a3);

        // ---- butterfly reduce over the 8 kc lanes (bits 0..2 of lane id)
        #pragma unroll
        for (int d = 1; d < 8; d <<= 1) {
            s0 += __shfl_xor_sync(0xffffffffu, s0, d);
            s1 += __shfl_xor_sync(0xffffffffu, s1, d);
            s2 += __shfl_xor_sync(0xffffffffu, s2, d);
            s3 += __shfl_xor_sync(0xffffffffu, s3, d);
        }

        const int nxt = cur ^ 1;
        if (tid == 0)
            asm volatile("mbarrier.arrive.expect_tx.shared.b64 _, [%0], %1;"
                         :: "r"(mbar_l), "r"(8192u) : "memory");

        if (kc < 4) {
            float s = (kc == 0) ? s0 : (kc == 1) ? s1 : (kc == 2) ? s2 : s3;
            float val = fmaxf(s + pv, 0.f);
            unsigned uval = __float_as_uint(val);
            #pragma unroll
            for (int r = 0; r < CLUSTER_S; ++r)
                asm volatile(
                    "st.async.shared::cluster.mbarrier::complete_tx::bytes.b32 "
                    "[%0], %1, [%2];"
                    :: "r"(nxt ? rh[1][r] : rh[0][r]), "r"(uval), "r"(rmb[r])
                    : "memory");
            houtP[(size_t)t * H_] = val;
            if (t + 1 < T_) pv = preP[(size_t)(t + 1) * H_];
        }

        // wait: all 2048 values (8192 B) for this step arrived
        {
            const unsigned par = (unsigned)(t & 1);
            asm volatile(
                "{\n\t.reg .pred P;\n\t"
                "WAIT_%=:\n\t"
                "mbarrier.try_wait.parity.acquire.cta.shared::cta.b64 P, [%0], %1, 0x989680;\n\t"
                "@!P bra WAIT_%=;\n\t}"
                :: "r"(mbar_l), "r"(par) : "memory");
        }
        cur = nxt;
    }

    asm volatile("barrier.cluster.arrive.aligned;" ::: "memory");
    asm volatile("barrier.cluster.wait.aligned;"   ::: "memory");
}

// ---------------------------------------------------------------------------
// C[M,N] = A[M,K] @ Bw[N,K]^T + bias1[N] + bias2[N]   (fp32 tiled SGEMM)
// ---------------------------------------------------------------------------
#define BM 128
#define BN 128
#define BK 8
#define TM 8
#define TN 8

__global__ void __launch_bounds__(256)
sgemm_bias_kernel(const float* __restrict__ A, const float* __restrict__ Bw,
                  const float* __restrict__ bias1, const float* __restrict__ bias2,
                  float* __restrict__ C, int M, int N, int K)
{
    __shared__ float As[BK][BM];
    __shared__ float Bs[BK][BN];

    const int tid  = threadIdx.x;
    const int bm   = blockIdx.x * BM;
    const int bn   = blockIdx.y * BN;
    const int lrow = tid >> 1;          // 0..127
    const int lc   = (tid & 1) * 4;     // 0 or 4
    const int tx   = tid & 15;
    const int ty   = tid >> 4;

    unsigned long long acc2[TM / 2][TN];
    #pragma unroll
    for (int i = 0; i < TM / 2; i++)
        #pragma unroll
        for (int jj = 0; jj < TN; jj++) acc2[i][jj] = 0ull;

    for (int k0 = 0; k0 < K; k0 += BK) {
        float4 av = *reinterpret_cast<const float4*>(
            &A[(size_t)(bm + lrow) * K + k0 + lc]);
        float4 bv = *reinterpret_cast<const float4*>(
            &Bw[(size_t)(bn + lrow) * K + k0 + lc]);
        __syncthreads();
        As[lc + 0][lrow] = av.x; As[lc + 1][lrow] = av.y;
        As[lc + 2][lrow] = av.z; As[lc + 3][lrow] = av.w;
        Bs[lc + 0][lrow] = bv.x; Bs[lc + 1][lrow] = bv.y;
        Bs[lc + 2][lrow] = bv.z; Bs[lc + 3][lrow] = bv.w;
        __syncthreads();

        #pragma unroll
        for (int kk = 0; kk < BK; ++kk) {
            ulonglong2 raA = *reinterpret_cast<const ulonglong2*>(&As[kk][ty * TM]);
            ulonglong2 raB = *reinterpret_cast<const ulonglong2*>(&As[kk][ty * TM + 4]);
            float4 rb0 = *reinterpret_cast<const float4*>(&Bs[kk][tx * TN]);
            float4 rb1 = *reinterpret_cast<const float4*>(&Bs[kk][tx * TN + 4]);
            unsigned long long ra[4] = { raA.x, raA.y, raB.x, raB.y };
            unsigned long long rbb[8];
            rbb[0] = dupf(rb0.x); rbb[1] = dupf(rb0.y);
            rbb[2] = dupf(rb0.z); rbb[3] = dupf(rb0.w);
            rbb[4] = dupf(rb1.x); rbb[5] = dupf(rb1.y);
            rbb[6] = dupf(rb1.z); rbb[7] = dupf(rb1.w);
            #pragma unroll
            for (int i2 = 0; i2 < 4; ++i2)
                #pragma unroll
                for (int jj = 0; jj < TN; ++jj)
                    ffma2(acc2[i2][jj], ra[i2], rbb[jj]);
        }
    }

    #pragma unroll
    for (int i2 = 0; i2 < TM / 2; ++i2) {
        const size_t row0 = (size_t)(bm + ty * TM + 2 * i2) * N;
        const size_t row1 = row0 + N;
        #pragma unroll
        for (int jj = 0; jj < TN; ++jj) {
            const int col = bn + tx * TN + jj;
            float lo = __uint_as_float((unsigned)(acc2[i2][jj] & 0xffffffffull));
            float hi = __uint_as_float((unsigned)(acc2[i2][jj] >> 32));
            float bsum = bias1[col] + bias2[col];
            C[row0 + col] = lo + bsum;
            C[row1 + col] = hi + bsum;
        }
    }
}

// ---------------------------------------------------------------------------
// out[b,c] = h1[b, T-1, :] . fc_w[c, :] + fc_b[c]
// ---------------------------------------------------------------------------
__global__ void __launch_bounds__(C_)
fc_kernel(const float* __restrict__ h, const float* __restrict__ fw,
          const float* __restrict__ fb, float* __restrict__ out)
{
    __shared__ float hv[H_];
    const int b = blockIdx.x;
    const int c = threadIdx.x;
    for (int k = c; k < H_; k += C_)
        hv[k] = h[((size_t)b * T_ + (T_ - 1)) * H_ + k];
    __syncthreads();

    const float* w = fw + (size_t)c * H_;
    float acc = 0.f;
    #pragma unroll 8
    for (int k = 0; k < H_; k += 4) {
        float4 wv = *reinterpret_cast<const float4*>(w + k);
        acc += wv.x * hv[k] + wv.y * hv[k + 1] + wv.z * hv[k + 2] + wv.w * hv[k + 3];
    }
    out[b * C_ + c] = acc + fb[c];
}

// ---------------------------------------------------------------------------
extern "C" void kernel_launch(void* const* d_in, const int* in_sizes, int n_in,
                              void* d_out, int out_size)
{
    const float* x     = (const float*)d_in[0];
    const float* W_ih0 = (const float*)d_in[1];
    const float* W_hh0 = (const float*)d_in[2];
    const float* b_ih0 = (const float*)d_in[3];
    const float* b_hh0 = (const float*)d_in[4];
    const float* W_ih1 = (const float*)d_in[5];
    const float* W_hh1 = (const float*)d_in[6];
    const float* b_ih1 = (const float*)d_in[7];
    const float* b_hh1 = (const float*)d_in[8];
    const float* fc_w  = (const float*)d_in[9];
    const float* fc_b  = (const float*)d_in[10];
    float* out = (float*)d_out;

    float *bufA, *bufB;
    cudaGetSymbolAddress((void**)&bufA, g_bufA);
    cudaGetSymbolAddress((void**)&bufB, g_bufB);

    const int M = B_ * T_;
    dim3 gemm_grid(M / BM, H_ / BN);

    // pre0 = x @ W_ih0^T + b_ih0 + b_hh0
    sgemm_bias_kernel<<<gemm_grid, 256>>>(x, W_ih0, b_ih0, b_hh0, bufA,
                                          M, H_, IN_);
    // layer 0 scan: bufA(pre) -> bufB(h0)
    scan_kernel<<<dim3(16 * CLUSTER_S), SCAN_THREADS>>>(W_hh0, bufA, bufB);
    // pre1 = h0 @ W_ih1^T + b_ih1 + b_hh1
    sgemm_bias_kernel<<<gemm_grid, 256>>>(bufB, W_ih1, b_ih1, b_hh1, bufA,
                                          M, H_, H_);
    // layer 1 scan: bufA(pre) -> bufA(h1, in-place)
    scan_kernel<<<dim3(16 * CLUSTER_S), SCAN_THREADS>>>(W_hh1, bufA, bufA);
    // out = h1[:, -1, :] @ fc_w^T + fc_b
    fc_kernel<<<B_, C_>>>(bufA, fc_w, fc_b, out);
}